// round 7
// baseline (speedup 1.0000x reference)
#include <cuda_runtime.h>
#include <cuda_fp16.h>
#include <math.h>
#include <stdint.h>

// ---------------------------------------------------------------------------
// NAS-controller LSTM, persistent kernel v7 (tensor-core GEMV).
//  - weights fp32->fp16 swizzled ONCE into mma a-frag layout (g_Ws, 96MB,
//    L2-resident): hot loop = 1 LDG.128 + 2 LDS.32 + 1 HMMA per 512B tile
//  - 16-row tiles, K-split 2; partials via atomicAdd (2 addends per row ->
//    bitwise deterministic); dot buffers 4-deep parity ring, zeroed by idle
//    warps two grid-syncs after last read
//  - no TMA, no mbarriers, no smem weight staging
//  - threefry2x32 partitionable path (verified bit-exact)
// ---------------------------------------------------------------------------

#define HD    2048
#define H4    8192
#define ED    512
#define TT    48
#define MAXS  8
#define NEMB  23
#define NTH   1024
#define NWARPS 32
#define TINYF 1.17549435e-38f

#define NTILE    512                 // 16-row tiles per matrix
#define KTILES   128                 // k16 tiles per row (K=2048)
#define TILE_U4  (KTILES * 32)       // uint4 per 16-row tile row-strip

// ------------------------- device scratch ----------------------------------
__device__ __half   g_Ws[3u * NTILE * KTILES * 256];  // swizzled fp16 (96MB)
__device__ float    g_P1[NEMB * H4];
__device__ float    g_d1[4 * H4];    // Whh1.h1 partials, 4-step parity ring
__device__ float    g_d2[4 * H4];    // Whh2.h2
__device__ float    g_d3[4 * H4];    // Wih2.h1new
__device__ float    g_b1[H4];        // bih1+bhh1
__device__ float    g_b2[H4];        // bih2+bhh2
__device__ unsigned g_count = 0;
__device__ unsigned g_gen   = 0;

// ------------------------- grid barrier (tight poll) ------------------------
__device__ __forceinline__ void grid_sync() {
  __threadfence();
  __syncthreads();
  if (threadIdx.x == 0) {
    volatile unsigned* vg = (volatile unsigned*)&g_gen;
    unsigned gen = *vg;
    __threadfence();
    if (atomicAdd(&g_count, 1u) == (unsigned)(gridDim.x - 1)) {
      g_count = 0u;
      __threadfence();
      atomicAdd(&g_gen, 1u);
    } else {
      while (*vg == gen) { }
    }
  }
  __syncthreads();
}

// ------------------------- threefry2x32 (verified exact) --------------------
__device__ __forceinline__ unsigned rotl32(unsigned x, int r) {
  return (x << r) | (x >> (32 - r));
}
__device__ __forceinline__ void threefry2x32(unsigned k0, unsigned k1,
                                             unsigned x0, unsigned x1,
                                             unsigned* o0, unsigned* o1) {
  unsigned ks0 = k0, ks1 = k1, ks2 = k0 ^ k1 ^ 0x1BD11BDAu;
  x0 += ks0; x1 += ks1;
  x0 += x1; x1 = rotl32(x1, 13); x1 ^= x0;
  x0 += x1; x1 = rotl32(x1, 15); x1 ^= x0;
  x0 += x1; x1 = rotl32(x1, 26); x1 ^= x0;
  x0 += x1; x1 = rotl32(x1, 6);  x1 ^= x0;
  x0 += ks1; x1 += ks2 + 1u;
  x0 += x1; x1 = rotl32(x1, 17); x1 ^= x0;
  x0 += x1; x1 = rotl32(x1, 29); x1 ^= x0;
  x0 += x1; x1 = rotl32(x1, 16); x1 ^= x0;
  x0 += x1; x1 = rotl32(x1, 24); x1 ^= x0;
  x0 += ks2; x1 += ks0 + 2u;
  x0 += x1; x1 = rotl32(x1, 13); x1 ^= x0;
  x0 += x1; x1 = rotl32(x1, 15); x1 ^= x0;
  x0 += x1; x1 = rotl32(x1, 26); x1 ^= x0;
  x0 += x1; x1 = rotl32(x1, 6);  x1 ^= x0;
  x0 += ks0; x1 += ks1 + 3u;
  x0 += x1; x1 = rotl32(x1, 17); x1 ^= x0;
  x0 += x1; x1 = rotl32(x1, 29); x1 ^= x0;
  x0 += x1; x1 = rotl32(x1, 16); x1 ^= x0;
  x0 += x1; x1 = rotl32(x1, 24); x1 ^= x0;
  x0 += ks1; x1 += ks2 + 4u;
  x0 += x1; x1 = rotl32(x1, 13); x1 ^= x0;
  x0 += x1; x1 = rotl32(x1, 15); x1 ^= x0;
  x0 += x1; x1 = rotl32(x1, 26); x1 ^= x0;
  x0 += x1; x1 = rotl32(x1, 6);  x1 ^= x0;
  x0 += ks2; x1 += ks0 + 5u;
  *o0 = x0; *o1 = x1;
}

__device__ __forceinline__ float sigm(float x) { return 1.0f / (1.0f + expf(-x)); }

// ------------------------- mma work unit ------------------------------------
// 16 rows (tile base R), K half `kh` (1024 K = 64 k16 tiles). Weights in
// a-frag-swizzled g_Ws; h (fp16) broadcast from smem as b-frags; fp32 accum;
// lanes %4==0 hold D column 0 -> 2 atomicAdds each (rows g, g+8).
__device__ __forceinline__ void mma_unit(const uint4* __restrict__ w4,
                                         const __half* __restrict__ hsm,
                                         int kh, float* __restrict__ dst,
                                         int R, int lane) {
  const unsigned* hp = (const unsigned*)hsm + (kh << 9) + (lane & 3);
  float d0 = 0.f, d1 = 0.f, d2 = 0.f, d3 = 0.f;
#pragma unroll 8
  for (int i = 0; i < 64; i++) {
    uint4 a = __ldcg(w4 + (size_t)i * 32);
    unsigned b0 = hp[i * 8];
    unsigned b1 = hp[i * 8 + 4];
    asm volatile(
        "mma.sync.aligned.m16n8k16.row.col.f32.f16.f16.f32 "
        "{%0,%1,%2,%3}, {%4,%5,%6,%7}, {%8,%9}, {%0,%1,%2,%3};"
        : "+f"(d0), "+f"(d1), "+f"(d2), "+f"(d3)
        : "r"(a.x), "r"(a.y), "r"(a.z), "r"(a.w), "r"(b0), "r"(b1));
  }
  if ((lane & 3) == 0) {
    atomicAdd(&dst[R + (lane >> 2)], d0);
    atomicAdd(&dst[R + (lane >> 2) + 8], d2);
  }
}

// ------------------------- main persistent kernel ---------------------------
__global__ void __launch_bounds__(NTH, 1)
nas_lstm_kernel(const float* __restrict__ emb,
                const float* __restrict__ Wih1, const float* __restrict__ Whh1,
                const float* __restrict__ bih1, const float* __restrict__ bhh1,
                const float* __restrict__ Wih2, const float* __restrict__ Whh2,
                const float* __restrict__ bih2, const float* __restrict__ bhh2,
                const float* __restrict__ Wout, const float* __restrict__ bout,
                float* __restrict__ out) {
  __shared__ __align__(16) __half sAh[HD];   // h1 fp16
  __shared__ __align__(16) __half sBh[HD];   // h2 fp16
  __shared__ float sLG[8];
  __shared__ int   sAR;

  const int tid  = threadIdx.x;
  const int b    = blockIdx.x;
  const int w    = tid >> 5;
  const int lane = tid & 31;
  const int nblk = gridDim.x;
  const int totw = nblk * NWARPS;
  const int wg   = w * nblk + b;           // warp-major global warp id

  // ---------------- init ----------------
  for (int i = tid; i < HD; i += NTH) {
    sAh[i] = __float2half_rn(0.f);
    sBh[i] = __float2half_rn(0.f);
  }
  if (tid == 0) sAR = -1;
  __syncthreads();

  // zero all dot parity rings + combined biases (grid-strided, disjoint)
  for (int i = b * NTH + tid; i < 4 * H4; i += nblk * NTH) {
    g_d1[i] = 0.f; g_d2[i] = 0.f; g_d3[i] = 0.f;
  }
  for (int i = b * NTH + tid; i < H4; i += nblk * NTH) {
    g_b1[i] = bih1[i] + bhh1[i];
    g_b2[i] = bih2[i] + bhh2[i];
  }

  // fp32 -> fp16 a-frag swizzle of the three streamed matrices.
  // unit q = [mat(3)][tile(512)][rpair(8)][cg(512)]; cg = 4 cols.
  {
    uint2* dst = (uint2*)g_Ws;
    const long NQ = 3L * 512 * 8 * 512;
    for (long q = (long)b * NTH + tid; q < NQ; q += (long)nblk * NTH) {
      const int cg   = (int)(q & 511);
      const int r    = (int)((q >> 9) & 7);
      const int tile = (int)((q >> 12) & 511);
      const int mat  = (int)(q >> 21);
      const int c    = cg << 2;
      const int j    = cg >> 2;
      const int L    = (r << 2) + ((cg & 1) << 1);
      const int o    = (cg & 2) ? 1 : 0;
      const float* src = (mat == 0) ? Whh1 : (mat == 1) ? Whh2 : Wih2;
      const int R1 = (tile << 4) + r;
      float4 v1 = __ldg((const float4*)(src + ((size_t)R1 << 11) + c));
      float4 v2 = __ldg((const float4*)(src + ((size_t)(R1 + 8) << 11) + c));
      __half2 a1 = __floats2half2_rn(v1.x, v1.y);
      __half2 a2 = __floats2half2_rn(v2.x, v2.y);
      __half2 b1h = __floats2half2_rn(v1.z, v1.w);
      __half2 b2h = __floats2half2_rn(v2.z, v2.w);
      const long blk = ((long)(mat << 9 | tile) * 128 + j) * 64;
      uint2 u2a, u2b;
      u2a.x = *(unsigned*)&a1; u2a.y = *(unsigned*)&a2;
      u2b.x = *(unsigned*)&b1h; u2b.y = *(unsigned*)&b2h;
      dst[blk + (L << 1) + o]       = u2a;
      dst[blk + ((L + 1) << 1) + o] = u2b;
    }
  }

  // P1 = emb @ Wih1^T (warp per row, fp32)
  for (int r = wg; r < H4; r += totw) {
    float wreg[16];
    const float* wrow = Wih1 + (size_t)r * ED;
#pragma unroll
    for (int i = 0; i < 16; i++) wreg[i] = wrow[lane + i * 32];
    for (int m = 0; m < NEMB; m++) {
      const float* er = emb + m * ED;
      float p = 0.f;
#pragma unroll
      for (int i = 0; i < 16; i++) p += wreg[i] * er[lane + i * 32];
#pragma unroll
      for (int off = 16; off; off >>= 1) p += __shfl_xor_sync(0xffffffffu, p, off);
      if (lane == 0) g_P1[m * H4 + r] = p;
    }
  }
  grid_sync();

  float c1a = 0.f, c1b = 0.f, c2a = 0.f, c2b = 0.f;
  const int sizes[4] = {8, 6, 4, 5};
  const int offs[4]  = {0, 8, 14, 18};

  for (int t = 0; t < TT; t++) {
    const int pb = t & 3;
    float* d1 = g_d1 + pb * H4;
    float* d2 = g_d2 + pb * H4;
    float* d3 = g_d3 + pb * H4;

    // -------- segment A: Whh1.h1prev + Whh2.h2prev (2048 units) --------
    for (int u = wg; u < 2048; u += totw) {
      const int tile = u >> 1, kh = u & 1;
      const int m = (tile < 512) ? 0 : 1;
      const int T = tile & 511;
      const uint4* w4 = (const uint4*)g_Ws +
                        ((size_t)((m << 9) | T) * 128 + (kh << 6)) * 32 + lane;
      mma_unit(w4, (m == 0) ? sAh : sBh, kh, (m == 0) ? d1 : d2, T << 4, lane);
    }
    grid_sync();

    // -------- act1: h1 (bias + P1; redundant per block) --------
    {
      const int arow = sAR;
      const float* P = (arow >= 0) ? (g_P1 + (size_t)arow * H4) : (const float*)0;
      int u = tid;
      float di = __ldcg(&d1[u])        + __ldcg(&g_b1[u]);
      float df = __ldcg(&d1[u + 2048]) + __ldcg(&g_b1[u + 2048]);
      float dg = __ldcg(&d1[u + 4096]) + __ldcg(&g_b1[u + 4096]);
      float dz = __ldcg(&d1[u + 6144]) + __ldcg(&g_b1[u + 6144]);
      if (P) {
        di += __ldcg(&P[u]);        df += __ldcg(&P[u + 2048]);
        dg += __ldcg(&P[u + 4096]); dz += __ldcg(&P[u + 6144]);
      }
      float c = sigm(df) * c1a + sigm(di) * tanhf(dg);
      c1a = c;
      sAh[u] = __float2half_rn(sigm(dz) * tanhf(c));
      u = tid + NTH;
      di = __ldcg(&d1[u])        + __ldcg(&g_b1[u]);
      df = __ldcg(&d1[u + 2048]) + __ldcg(&g_b1[u + 2048]);
      dg = __ldcg(&d1[u + 4096]) + __ldcg(&g_b1[u + 4096]);
      dz = __ldcg(&d1[u + 6144]) + __ldcg(&g_b1[u + 6144]);
      if (P) {
        di += __ldcg(&P[u]);        df += __ldcg(&P[u + 2048]);
        dg += __ldcg(&P[u + 4096]); dz += __ldcg(&P[u + 6144]);
      }
      c = sigm(df) * c1b + sigm(di) * tanhf(dg);
      c1b = c;
      sAh[u] = __float2half_rn(sigm(dz) * tanhf(c));
    }
    __syncthreads();

    // -------- segment B: Wih2.h1new (1024 units) + parity zeroing --------
    for (int u = wg; u < 1024; u += totw) {
      const int tile = u >> 1, kh = u & 1;
      const uint4* w4 = (const uint4*)g_Ws +
                        ((size_t)((2 << 9) | tile) * 128 + (kh << 6)) * 32 + lane;
      mma_unit(w4, sAh, kh, d3, tile << 4, lane);
    }
    if (w >= 8) {
      // zero parity (t+3)&3 (last read two grid-syncs ago; reused at t+3/t+4)
      const int pz = (t + 3) & 3;
      float* z1 = g_d1 + pz * H4;
      float* z2 = g_d2 + pz * H4;
      float* z3 = g_d3 + pz * H4;
      for (int z = (w - 8) * 32 + lane + b * 768; z < 3 * H4; z += nblk * 768) {
        if (z < H4)            __stcg(&z1[z], 0.f);
        else if (z < 2 * H4)   __stcg(&z2[z - H4], 0.f);
        else                   __stcg(&z3[z - 2 * H4], 0.f);
      }
    }
    grid_sync();

    // -------- act2: h2 --------
    {
      int u = tid;
      float di = __ldcg(&d2[u])        + __ldcg(&d3[u])        + __ldcg(&g_b2[u]);
      float df = __ldcg(&d2[u + 2048]) + __ldcg(&d3[u + 2048]) + __ldcg(&g_b2[u + 2048]);
      float dg = __ldcg(&d2[u + 4096]) + __ldcg(&d3[u + 4096]) + __ldcg(&g_b2[u + 4096]);
      float dz = __ldcg(&d2[u + 6144]) + __ldcg(&d3[u + 6144]) + __ldcg(&g_b2[u + 6144]);
      float c = sigm(df) * c2a + sigm(di) * tanhf(dg);
      c2a = c;
      sBh[u] = __float2half_rn(sigm(dz) * tanhf(c));
      u = tid + NTH;
      di = __ldcg(&d2[u])        + __ldcg(&d3[u])        + __ldcg(&g_b2[u]);
      df = __ldcg(&d2[u + 2048]) + __ldcg(&d3[u + 2048]) + __ldcg(&g_b2[u + 2048]);
      dg = __ldcg(&d2[u + 4096]) + __ldcg(&d3[u + 4096]) + __ldcg(&g_b2[u + 4096]);
      dz = __ldcg(&d2[u + 6144]) + __ldcg(&d3[u + 6144]) + __ldcg(&g_b2[u + 6144]);
      c = sigm(df) * c2b + sigm(di) * tanhf(dg);
      c2b = c;
      sBh[u] = __float2half_rn(sigm(dz) * tanhf(c));
    }
    __syncthreads();

    // -------- logits (8 parallel warps, redundant per block) --------
    if (w < 8) {
      const float4* wr = (const float4*)(Wout + ((size_t)t * MAXS + w) * HD);
      const __half2* h2p = (const __half2*)sBh;
      float p = 0.f;
#pragma unroll 4
      for (int i = lane; i < HD / 4; i += 32) {
        float4 a = __ldg(&wr[i]);
        float2 xf = __half22float2(h2p[2 * i]);
        float2 yf = __half22float2(h2p[2 * i + 1]);
        p += a.x * xf.x + a.y * xf.y + a.z * yf.x + a.w * yf.y;
      }
#pragma unroll
      for (int off = 16; off; off >>= 1) p += __shfl_xor_sync(0xffffffffu, p, off);
      if (lane == 0) sLG[w] = p + bout[t * MAXS + w];
    }
    __syncthreads();

    // -------- finalize sample (thread 0) --------
    if (tid == 0) {
      const int tp = t & 3;
      const int sz = sizes[tp];
      float l[8];
#pragma unroll
      for (int j = 0; j < 8; j++) l[j] = (j < sz) ? sLG[j] : -1e9f;

      unsigned k0, k1;
      threefry2x32(0u, 1u, 0u, (unsigned)t, &k0, &k1);
      unsigned bits[8];
#pragma unroll
      for (int i = 0; i < 8; i++) {
        unsigned a, bb;
        threefry2x32(k0, k1, 0u, (unsigned)i, &a, &bb);
        bits[i] = a ^ bb;
      }
      float gmb[8];
#pragma unroll
      for (int j = 0; j < 8; j++) {
        unsigned fb = (bits[j] >> 9) | 0x3f800000u;
        float uu = __uint_as_float(fb) - 1.0f;
        uu = fmaxf(TINYF, uu + TINYF);
        gmb[j] = -logf(-logf(uu));
      }
      int best = 0;
      float bv = l[0] + gmb[0];
#pragma unroll
      for (int j = 1; j < 8; j++) {
        float v = l[j] + gmb[j];
        if (v > bv) { bv = v; best = j; }
      }
      float m = l[0];
#pragma unroll
      for (int j = 1; j < 8; j++) m = fmaxf(m, l[j]);
      float s = 0.f;
#pragma unroll
      for (int j = 0; j < 8; j++) s += expf(l[j] - m);
      float prob = expf(l[best] - m) / s;

      sAR = offs[tp] + best;
      if (b == 0) {
        out[t]      = (float)best;
        out[TT + t] = prob;
      }
    }
    __syncthreads();
  }
}

// ------------------------- launch -------------------------------------------
extern "C" void kernel_launch(void* const* d_in, const int* in_sizes, int n_in,
                              void* d_out, int out_size) {
  const float* emb  = (const float*)d_in[0];
  const float* Wih1 = (const float*)d_in[1];
  const float* Whh1 = (const float*)d_in[2];
  const float* bih1 = (const float*)d_in[3];
  const float* bhh1 = (const float*)d_in[4];
  const float* Wih2 = (const float*)d_in[5];
  const float* Whh2 = (const float*)d_in[6];
  const float* bih2 = (const float*)d_in[7];
  const float* bhh2 = (const float*)d_in[8];
  const float* Wout = (const float*)d_in[9];
  const float* bout = (const float*)d_in[10];
  (void)in_sizes; (void)n_in; (void)out_size;

  int dev = 0;
  cudaGetDevice(&dev);
  int sms = 0;
  cudaDeviceGetAttribute(&sms, cudaDevAttrMultiProcessorCount, dev);
  int occ = 0;
  cudaOccupancyMaxActiveBlocksPerMultiprocessor(&occ, nas_lstm_kernel, NTH, 0);
  if (occ < 1) occ = 1;
  int nblk = sms * occ;
  if (nblk > 128) nblk = 128;
  if (nblk < 1) nblk = 1;

  nas_lstm_kernel<<<nblk, NTH>>>(emb, Wih1, Whh1, bih1, bhh1,
                                 Wih2, Whh2, bih2, bhh2,
                                 Wout, bout, (float*)d_out);
}

// round 8
// speedup vs baseline: 1.2240x; 1.2240x over previous
#include <cuda_runtime.h>
#include <cuda_fp16.h>
#include <math.h>
#include <stdint.h>

// ---------------------------------------------------------------------------
// NAS-controller LSTM, persistent kernel v8 = v6 streaming + v7 tensor cores.
//  - weights fp32->fp16 swizzled ONCE into mma a-frag layout (g_Ws, 96MB,
//    L2-resident); each 16row x 1024K unit = 32KB contiguous
//  - per-WARP TMA rings (4 x 2KB slices) feed HMMA directly from smem:
//    per 2KB slice = 4 x (LDS.128 + 2 LDS.32 + mma.m16n8k16), fp32 accum
//  - warps 0-15: segA units (Whh1,Whh2); 16-23: segB units (Wih2, ring
//    prefetched across phases); 24-31: parity-ring zeroing
//  - partials via atomicAdd (exactly 2 addends/row -> deterministic)
//  - threefry2x32 partitionable path (verified bit-exact)
// ---------------------------------------------------------------------------

#define HD    2048
#define H4    8192
#define ED    512
#define TT    48
#define MAXS  8
#define NEMB  23
#define NTH   1024
#define NWARPS 32
#define TINYF 1.17549435e-38f

#define NSLOT    4
#define SLICE_B  2048

// smem layout (bytes)
#define OFF_SAH   0                 // h1 fp16 (4096)
#define OFF_SBH   4096              // h2 fp16
#define OFF_LG    8192
#define OFF_AROW  8224
#define OFF_MBAR  8240              // 24*4*8 = 768
#define OFF_RING  9216              // 24*4*2048 = 196608
#define SMEM_TOTAL (OFF_RING + 24 * NSLOT * SLICE_B)   // 205824

// ------------------------- device scratch ----------------------------------
__device__ __half   g_Ws[3u * 512 * 128 * 256];  // swizzled fp16 (96MB)
__device__ float    g_P1[NEMB * H4];
__device__ float    g_d1[4 * H4];    // Whh1.h1 partials, 4-step parity ring
__device__ float    g_d2[4 * H4];    // Whh2.h2
__device__ float    g_d3[4 * H4];    // Wih2.h1new
__device__ float    g_b1[H4];
__device__ float    g_b2[H4];
__device__ unsigned g_count = 0;
__device__ unsigned g_gen   = 0;

// ------------------------- grid barrier (tight poll) ------------------------
__device__ __forceinline__ void grid_sync() {
  __threadfence();
  __syncthreads();
  if (threadIdx.x == 0) {
    volatile unsigned* vg = (volatile unsigned*)&g_gen;
    unsigned gen = *vg;
    __threadfence();
    if (atomicAdd(&g_count, 1u) == (unsigned)(gridDim.x - 1)) {
      g_count = 0u;
      __threadfence();
      atomicAdd(&g_gen, 1u);
    } else {
      while (*vg == gen) { }
    }
  }
  __syncthreads();
}

// ------------------------- mbarrier / bulk copy -----------------------------
__device__ __forceinline__ uint32_t smem_u32(const void* p) {
  uint32_t a;
  asm("{ .reg .u64 t; cvta.to.shared.u64 t, %1; cvt.u32.u64 %0, t; }"
      : "=r"(a) : "l"(p));
  return a;
}
__device__ __forceinline__ void mbar_init(uint32_t a, uint32_t cnt) {
  asm volatile("mbarrier.init.shared.b64 [%0], %1;" :: "r"(a), "r"(cnt) : "memory");
}
__device__ __forceinline__ void mbar_expect(uint32_t a, uint32_t tx) {
  asm volatile("mbarrier.arrive.expect_tx.shared.b64 _, [%0], %1;"
               :: "r"(a), "r"(tx) : "memory");
}
__device__ __forceinline__ void mbar_wait(uint32_t a, unsigned ph) {
  asm volatile(
      "{\n\t.reg .pred P;\n"
      "W%=:\n\t"
      "mbarrier.try_wait.parity.shared.b64 P, [%0], %1;\n\t"
      "@P bra D%=;\n\t"
      "bra W%=;\n"
      "D%=:\n\t}"
      :: "r"(a), "r"(ph) : "memory");
}
__device__ __forceinline__ void bulk_g2s(uint32_t dst, const void* src,
                                         uint32_t bytes, uint32_t bar) {
  asm volatile(
      "cp.async.bulk.shared::cluster.global.mbarrier::complete_tx::bytes "
      "[%0], [%1], %2, [%3];"
      :: "r"(dst), "l"(src), "r"(bytes), "r"(bar) : "memory");
}

// ------------------------- threefry2x32 (verified exact) --------------------
__device__ __forceinline__ unsigned rotl32(unsigned x, int r) {
  return (x << r) | (x >> (32 - r));
}
__device__ __forceinline__ void threefry2x32(unsigned k0, unsigned k1,
                                             unsigned x0, unsigned x1,
                                             unsigned* o0, unsigned* o1) {
  unsigned ks0 = k0, ks1 = k1, ks2 = k0 ^ k1 ^ 0x1BD11BDAu;
  x0 += ks0; x1 += ks1;
  x0 += x1; x1 = rotl32(x1, 13); x1 ^= x0;
  x0 += x1; x1 = rotl32(x1, 15); x1 ^= x0;
  x0 += x1; x1 = rotl32(x1, 26); x1 ^= x0;
  x0 += x1; x1 = rotl32(x1, 6);  x1 ^= x0;
  x0 += ks1; x1 += ks2 + 1u;
  x0 += x1; x1 = rotl32(x1, 17); x1 ^= x0;
  x0 += x1; x1 = rotl32(x1, 29); x1 ^= x0;
  x0 += x1; x1 = rotl32(x1, 16); x1 ^= x0;
  x0 += x1; x1 = rotl32(x1, 24); x1 ^= x0;
  x0 += ks2; x1 += ks0 + 2u;
  x0 += x1; x1 = rotl32(x1, 13); x1 ^= x0;
  x0 += x1; x1 = rotl32(x1, 15); x1 ^= x0;
  x0 += x1; x1 = rotl32(x1, 26); x1 ^= x0;
  x0 += x1; x1 = rotl32(x1, 6);  x1 ^= x0;
  x0 += ks0; x1 += ks1 + 3u;
  x0 += x1; x1 = rotl32(x1, 17); x1 ^= x0;
  x0 += x1; x1 = rotl32(x1, 29); x1 ^= x0;
  x0 += x1; x1 = rotl32(x1, 16); x1 ^= x0;
  x0 += x1; x1 = rotl32(x1, 24); x1 ^= x0;
  x0 += ks1; x1 += ks2 + 4u;
  x0 += x1; x1 = rotl32(x1, 13); x1 ^= x0;
  x0 += x1; x1 = rotl32(x1, 15); x1 ^= x0;
  x0 += x1; x1 = rotl32(x1, 26); x1 ^= x0;
  x0 += x1; x1 = rotl32(x1, 6);  x1 ^= x0;
  x0 += ks2; x1 += ks0 + 5u;
  *o0 = x0; *o1 = x1;
}

__device__ __forceinline__ float sigm(float x) { return 1.0f / (1.0f + expf(-x)); }

// unit decode: segA u in [0,2048): tile=u>>1, mat=tile>=512, T=tile&511, kh=u&1
//              segB u in [0,1024): mat=2, T=u>>1, kh=u&1
__device__ __forceinline__ const char* unit_src(int u, bool isB, int k4) {
  int mat, T, kh;
  if (isB) { mat = 2; T = u >> 1; kh = u & 1; }
  else     { int tile = u >> 1; mat = (tile >= 512) ? 1 : 0; T = tile & 511; kh = u & 1; }
  return (const char*)g_Ws + (((size_t)((mat << 9) | T)) << 16)
         + ((size_t)kh << 15) + ((size_t)k4 << 11);
}

__device__ __forceinline__ void issue_one(int lane, int* iss, int* s_iss,
                                          int L, int TOTAL, int id0, int stride,
                                          bool isB, uint32_t ring, uint32_t bar) {
  if (*iss >= TOTAL) return;
  const int slot = *iss & 3;
  if (lane == 0) {
    const int u = id0 + ((*s_iss) >> 4) * stride;
    const char* src = unit_src(u, isB, (*s_iss) & 15);
    mbar_expect(bar + slot * 8, SLICE_B);
    bulk_g2s(ring + slot * SLICE_B, src, SLICE_B, bar + slot * 8);
  }
  if (++(*s_iss) == L) *s_iss = 0;
  (*iss)++;
}

// ------------------------- main persistent kernel ---------------------------
__global__ void __launch_bounds__(NTH, 1)
nas_lstm_kernel(const float* __restrict__ emb,
                const float* __restrict__ Wih1, const float* __restrict__ Whh1,
                const float* __restrict__ bih1, const float* __restrict__ bhh1,
                const float* __restrict__ Wih2, const float* __restrict__ Whh2,
                const float* __restrict__ bih2, const float* __restrict__ bhh2,
                const float* __restrict__ Wout, const float* __restrict__ bout,
                float* __restrict__ out) {
  extern __shared__ __align__(16) char sm[];
  const uint32_t smu = smem_u32(sm);

  const int tid  = threadIdx.x;
  const int b    = blockIdx.x;
  const int w    = tid >> 5;
  const int lane = tid & 31;
  const int nblk = gridDim.x;
  const int totw = nblk * NWARPS;
  const int wgl  = w * nblk + b;          // warp-major id (for P1 init)

  __half* sAh = (__half*)(sm + OFF_SAH);
  __half* sBh = (__half*)(sm + OFF_SBH);
  float*  sLG = (float*)(sm + OFF_LG);
  int*    sAR = (int*)(sm + OFF_AROW);

  const bool isA = (w < 16);
  const bool isB = (w >= 16 && w < 24);
  const uint32_t bar  = smu + OFF_MBAR + (uint32_t)w * NSLOT * 8;
  const uint32_t ring = smu + OFF_RING + (uint32_t)w * NSLOT * SLICE_B;
  const int ringoff   = OFF_RING + w * NSLOT * SLICE_B;

  // per-warp unit accounting
  int id0 = 0, stride = 1, nu = 0;
  if (isA) {
    id0 = w * nblk + b; stride = 16 * nblk;
    nu = (id0 < 2048) ? ((2048 - 1 - id0) / stride + 1) : 0;
  } else if (isB) {
    id0 = (w - 16) * nblk + b; stride = 8 * nblk;
    nu = (id0 < 1024) ? ((1024 - 1 - id0) / stride + 1) : 0;
  }
  const int L = nu * 16;
  const int TOTAL = TT * L;

  // ---------------- init ----------------
  for (int i = tid; i < HD; i += NTH) {
    sAh[i] = __float2half_rn(0.f);
    sBh[i] = __float2half_rn(0.f);
  }
  for (int i = tid; i < 24 * NSLOT; i += NTH)
    mbar_init(smu + OFF_MBAR + (uint32_t)i * 8, 1u);
  if (tid == 0) *sAR = -1;
  __syncthreads();
  if (tid == 0)
    asm volatile("fence.proxy.async.shared::cta;" ::: "memory");

  // zero all dot parity rings + combined biases (grid-strided, disjoint)
  for (int i = b * NTH + tid; i < 4 * H4; i += nblk * NTH) {
    g_d1[i] = 0.f; g_d2[i] = 0.f; g_d3[i] = 0.f;
  }
  for (int i = b * NTH + tid; i < H4; i += nblk * NTH) {
    g_b1[i] = bih1[i] + bhh1[i];
    g_b2[i] = bih2[i] + bhh2[i];
  }

  // fp32 -> fp16 a-frag swizzle (verified in v7)
  {
    uint2* dst = (uint2*)g_Ws;
    const long NQ = 3L * 512 * 8 * 512;
    for (long q = (long)b * NTH + tid; q < NQ; q += (long)nblk * NTH) {
      const int cg   = (int)(q & 511);
      const int r    = (int)((q >> 9) & 7);
      const int tile = (int)((q >> 12) & 511);
      const int mat  = (int)(q >> 21);
      const int c    = cg << 2;
      const int j    = cg >> 2;
      const int Lr   = (r << 2) + ((cg & 1) << 1);
      const int o    = (cg & 2) ? 1 : 0;
      const float* src = (mat == 0) ? Whh1 : (mat == 1) ? Whh2 : Wih2;
      const int R1 = (tile << 4) + r;
      float4 v1 = __ldg((const float4*)(src + ((size_t)R1 << 11) + c));
      float4 v2 = __ldg((const float4*)(src + ((size_t)(R1 + 8) << 11) + c));
      __half2 a1 = __floats2half2_rn(v1.x, v1.y);
      __half2 a2 = __floats2half2_rn(v2.x, v2.y);
      __half2 b1h = __floats2half2_rn(v1.z, v1.w);
      __half2 b2h = __floats2half2_rn(v2.z, v2.w);
      const long blk = ((long)(mat << 9 | tile) * 128 + j) * 64;
      uint2 u2a, u2b;
      u2a.x = *(unsigned*)&a1; u2a.y = *(unsigned*)&a2;
      u2b.x = *(unsigned*)&b1h; u2b.y = *(unsigned*)&b2h;
      dst[blk + (Lr << 1) + o]       = u2a;
      dst[blk + ((Lr + 1) << 1) + o] = u2b;
    }
  }

  // P1 = emb @ Wih1^T (warp per row, fp32)
  for (int r = wgl; r < H4; r += totw) {
    float wreg[16];
    const float* wrow = Wih1 + (size_t)r * ED;
#pragma unroll
    for (int i = 0; i < 16; i++) wreg[i] = wrow[lane + i * 32];
    for (int m = 0; m < NEMB; m++) {
      const float* er = emb + m * ED;
      float p = 0.f;
#pragma unroll
      for (int i = 0; i < 16; i++) p += wreg[i] * er[lane + i * 32];
#pragma unroll
      for (int off = 16; off; off >>= 1) p += __shfl_xor_sync(0xffffffffu, p, off);
      if (lane == 0) g_P1[m * H4 + r] = p;
    }
  }
  grid_sync();   // g_Ws fully written before any TMA reads it

  // stream cursors
  int iss = 0, s_iss = 0, con_slot = 0;
  unsigned ph = 0;
  float c1a = 0.f, c1b = 0.f, c2a = 0.f, c2b = 0.f;

  // prologue: fill ring
  if (nu > 0)
    for (int k = 0; k < NSLOT; k++)
      issue_one(lane, &iss, &s_iss, L, TOTAL, id0, stride, isB, ring, bar);

  const int sizes[4] = {8, 6, 4, 5};
  const int offs[4]  = {0, 8, 14, 18};

  for (int t = 0; t < TT; t++) {
    const int pb = t & 3;
    float* d1 = g_d1 + pb * H4;
    float* d2 = g_d2 + pb * H4;
    float* d3 = g_d3 + pb * H4;

    // -------- segment A: Whh1.h1prev + Whh2.h2prev --------
    if (isA && nu > 0) {
      for (int k = 0; k < nu; k++) {
        const int u = id0 + k * stride;
        const int tile = u >> 1;
        const int mat = (tile >= 512) ? 1 : 0;
        const int T = tile & 511;
        const int kh = u & 1;
        const unsigned* hpk = (const unsigned*)(mat ? sBh : sAh) + (kh << 9) + (lane & 3);
        float* dst = mat ? d2 : d1;
        float e0 = 0.f, e1 = 0.f, e2 = 0.f, e3 = 0.f;
        for (int k4 = 0; k4 < 16; k4++) {
          const int slot = con_slot;
          mbar_wait(bar + slot * 8, (ph >> slot) & 1u);
          ph ^= (1u << slot);
          const uint4* wp = (const uint4*)(sm + ringoff + slot * SLICE_B) + lane;
#pragma unroll
          for (int j = 0; j < 4; j++) {
            uint4 a = wp[j * 32];
            unsigned f0 = hpk[(k4 << 5) + (j << 3)];
            unsigned f1 = hpk[(k4 << 5) + (j << 3) + 4];
            asm volatile(
                "mma.sync.aligned.m16n8k16.row.col.f32.f16.f16.f32 "
                "{%0,%1,%2,%3}, {%4,%5,%6,%7}, {%8,%9}, {%0,%1,%2,%3};"
                : "+f"(e0), "+f"(e1), "+f"(e2), "+f"(e3)
                : "r"(a.x), "r"(a.y), "r"(a.z), "r"(a.w), "r"(f0), "r"(f1));
          }
          con_slot = (con_slot + 1) & 3;
          issue_one(lane, &iss, &s_iss, L, TOTAL, id0, stride, isB, ring, bar);
        }
        if ((lane & 3) == 0) {
          atomicAdd(&dst[(T << 4) + (lane >> 2)], e0);
          atomicAdd(&dst[(T << 4) + 8 + (lane >> 2)], e2);
        }
      }
    }
    grid_sync();

    // -------- act1: h1 (bias + P1; redundant per block) --------
    {
      const int arow = *sAR;
      const float* P = (arow >= 0) ? (g_P1 + (size_t)arow * H4) : (const float*)0;
      int u = tid;
      float di = __ldcg(&d1[u])        + __ldcg(&g_b1[u]);
      float df = __ldcg(&d1[u + 2048]) + __ldcg(&g_b1[u + 2048]);
      float dg = __ldcg(&d1[u + 4096]) + __ldcg(&g_b1[u + 4096]);
      float dz = __ldcg(&d1[u + 6144]) + __ldcg(&g_b1[u + 6144]);
      if (P) {
        di += __ldcg(&P[u]);        df += __ldcg(&P[u + 2048]);
        dg += __ldcg(&P[u + 4096]); dz += __ldcg(&P[u + 6144]);
      }
      float c = sigm(df) * c1a + sigm(di) * tanhf(dg);
      c1a = c;
      sAh[u] = __float2half_rn(sigm(dz) * tanhf(c));
      u = tid + NTH;
      di = __ldcg(&d1[u])        + __ldcg(&g_b1[u]);
      df = __ldcg(&d1[u + 2048]) + __ldcg(&g_b1[u + 2048]);
      dg = __ldcg(&d1[u + 4096]) + __ldcg(&g_b1[u + 4096]);
      dz = __ldcg(&d1[u + 6144]) + __ldcg(&g_b1[u + 6144]);
      if (P) {
        di += __ldcg(&P[u]);        df += __ldcg(&P[u + 2048]);
        dg += __ldcg(&P[u + 4096]); dz += __ldcg(&P[u + 6144]);
      }
      c = sigm(df) * c1b + sigm(di) * tanhf(dg);
      c1b = c;
      sAh[u] = __float2half_rn(sigm(dz) * tanhf(c));
    }
    __syncthreads();

    // -------- segment B: Wih2.h1new + parity zeroing --------
    if (isB && nu > 0) {
      for (int k = 0; k < nu; k++) {
        const int u = id0 + k * stride;
        const int T = u >> 1;
        const int kh = u & 1;
        const unsigned* hpk = (const unsigned*)sAh + (kh << 9) + (lane & 3);
        float e0 = 0.f, e1 = 0.f, e2 = 0.f, e3 = 0.f;
        for (int k4 = 0; k4 < 16; k4++) {
          const int slot = con_slot;
          mbar_wait(bar + slot * 8, (ph >> slot) & 1u);
          ph ^= (1u << slot);
          const uint4* wp = (const uint4*)(sm + ringoff + slot * SLICE_B) + lane;
#pragma unroll
          for (int j = 0; j < 4; j++) {
            uint4 a = wp[j * 32];
            unsigned f0 = hpk[(k4 << 5) + (j << 3)];
            unsigned f1 = hpk[(k4 << 5) + (j << 3) + 4];
            asm volatile(
                "mma.sync.aligned.m16n8k16.row.col.f32.f16.f16.f32 "
                "{%0,%1,%2,%3}, {%4,%5,%6,%7}, {%8,%9}, {%0,%1,%2,%3};"
                : "+f"(e0), "+f"(e1), "+f"(e2), "+f"(e3)
                : "r"(a.x), "r"(a.y), "r"(a.z), "r"(a.w), "r"(f0), "r"(f1));
          }
          con_slot = (con_slot + 1) & 3;
          issue_one(lane, &iss, &s_iss, L, TOTAL, id0, stride, isB, ring, bar);
        }
        if ((lane & 3) == 0) {
          atomicAdd(&d3[(T << 4) + (lane >> 2)], e0);
          atomicAdd(&d3[(T << 4) + 8 + (lane >> 2)], e2);
        }
      }
    } else if (w >= 24) {
      // zero parity (t+3)&3 (verified schedule from v7)
      const int pz = (t + 3) & 3;
      float* z1 = g_d1 + pz * H4;
      float* z2 = g_d2 + pz * H4;
      float* z3 = g_d3 + pz * H4;
      for (int z = (w - 24) * 32 + lane + b * 256; z < 3 * H4; z += nblk * 256) {
        if (z < H4)            __stcg(&z1[z], 0.f);
        else if (z < 2 * H4)   __stcg(&z2[z - H4], 0.f);
        else                   __stcg(&z3[z - 2 * H4], 0.f);
      }
    }
    grid_sync();

    // -------- act2: h2 --------
    {
      int u = tid;
      float di = __ldcg(&d2[u])        + __ldcg(&d3[u])        + __ldcg(&g_b2[u]);
      float df = __ldcg(&d2[u + 2048]) + __ldcg(&d3[u + 2048]) + __ldcg(&g_b2[u + 2048]);
      float dg = __ldcg(&d2[u + 4096]) + __ldcg(&d3[u + 4096]) + __ldcg(&g_b2[u + 4096]);
      float dz = __ldcg(&d2[u + 6144]) + __ldcg(&d3[u + 6144]) + __ldcg(&g_b2[u + 6144]);
      float c = sigm(df) * c2a + sigm(di) * tanhf(dg);
      c2a = c;
      sBh[u] = __float2half_rn(sigm(dz) * tanhf(c));
      u = tid + NTH;
      di = __ldcg(&d2[u])        + __ldcg(&d3[u])        + __ldcg(&g_b2[u]);
      df = __ldcg(&d2[u + 2048]) + __ldcg(&d3[u + 2048]) + __ldcg(&g_b2[u + 2048]);
      dg = __ldcg(&d2[u + 4096]) + __ldcg(&d3[u + 4096]) + __ldcg(&g_b2[u + 4096]);
      dz = __ldcg(&d2[u + 6144]) + __ldcg(&d3[u + 6144]) + __ldcg(&g_b2[u + 6144]);
      c = sigm(df) * c2b + sigm(di) * tanhf(dg);
      c2b = c;
      sBh[u] = __float2half_rn(sigm(dz) * tanhf(c));
    }
    __syncthreads();

    // -------- logits (8 parallel warps, redundant per block) --------
    if (w < 8) {
      const float4* wr = (const float4*)(Wout + ((size_t)t * MAXS + w) * HD);
      const __half2* h2p = (const __half2*)sBh;
      float p = 0.f;
#pragma unroll 4
      for (int i = lane; i < HD / 4; i += 32) {
        float4 a = __ldg(&wr[i]);
        float2 xf = __half22float2(h2p[2 * i]);
        float2 yf = __half22float2(h2p[2 * i + 1]);
        p += a.x * xf.x + a.y * xf.y + a.z * yf.x + a.w * yf.y;
      }
#pragma unroll
      for (int off = 16; off; off >>= 1) p += __shfl_xor_sync(0xffffffffu, p, off);
      if (lane == 0) sLG[w] = p + bout[t * MAXS + w];
    }
    __syncthreads();

    // -------- finalize sample (thread 0) --------
    if (tid == 0) {
      const int tp = t & 3;
      const int sz = sizes[tp];
      float l[8];
#pragma unroll
      for (int j = 0; j < 8; j++) l[j] = (j < sz) ? sLG[j] : -1e9f;

      unsigned k0, k1;
      threefry2x32(0u, 1u, 0u, (unsigned)t, &k0, &k1);
      unsigned bits[8];
#pragma unroll
      for (int i = 0; i < 8; i++) {
        unsigned a, bb;
        threefry2x32(k0, k1, 0u, (unsigned)i, &a, &bb);
        bits[i] = a ^ bb;
      }
      float gmb[8];
#pragma unroll
      for (int j = 0; j < 8; j++) {
        unsigned fb = (bits[j] >> 9) | 0x3f800000u;
        float uu = __uint_as_float(fb) - 1.0f;
        uu = fmaxf(TINYF, uu + TINYF);
        gmb[j] = -logf(-logf(uu));
      }
      int best = 0;
      float bv = l[0] + gmb[0];
#pragma unroll
      for (int j = 1; j < 8; j++) {
        float v = l[j] + gmb[j];
        if (v > bv) { bv = v; best = j; }
      }
      float m = l[0];
#pragma unroll
      for (int j = 1; j < 8; j++) m = fmaxf(m, l[j]);
      float s = 0.f;
#pragma unroll
      for (int j = 0; j < 8; j++) s += expf(l[j] - m);
      float prob = expf(l[best] - m) / s;

      *sAR = offs[tp] + best;
      if (b == 0) {
        out[t]      = (float)best;
        out[TT + t] = prob;
      }
    }
    __syncthreads();
  }
}

// ------------------------- launch -------------------------------------------
extern "C" void kernel_launch(void* const* d_in, const int* in_sizes, int n_in,
                              void* d_out, int out_size) {
  const float* emb  = (const float*)d_in[0];
  const float* Wih1 = (const float*)d_in[1];
  const float* Whh1 = (const float*)d_in[2];
  const float* bih1 = (const float*)d_in[3];
  const float* bhh1 = (const float*)d_in[4];
  const float* Wih2 = (const float*)d_in[5];
  const float* Whh2 = (const float*)d_in[6];
  const float* bih2 = (const float*)d_in[7];
  const float* bhh2 = (const float*)d_in[8];
  const float* Wout = (const float*)d_in[9];
  const float* bout = (const float*)d_in[10];
  (void)in_sizes; (void)n_in; (void)out_size;

  static int configured = 0;
  if (!configured) {
    cudaFuncSetAttribute(nas_lstm_kernel,
                         cudaFuncAttributeMaxDynamicSharedMemorySize, SMEM_TOTAL);
    configured = 1;
  }

  int dev = 0;
  cudaGetDevice(&dev);
  int sms = 0;
  cudaDeviceGetAttribute(&sms, cudaDevAttrMultiProcessorCount, dev);
  int occ = 0;
  cudaOccupancyMaxActiveBlocksPerMultiprocessor(&occ, nas_lstm_kernel, NTH,
                                                SMEM_TOTAL);
  if (occ < 1) occ = 1;
  int nblk = sms * occ;
  if (nblk > 128) nblk = 128;
  if (nblk < 1) nblk = 1;

  nas_lstm_kernel<<<nblk, NTH, SMEM_TOTAL>>>(emb, Wih1, Whh1, bih1, bhh1,
                                             Wih2, Whh2, bih2, bhh2,
                                             Wout, bout, (float*)d_out);
}